// round 8
// baseline (speedup 1.0000x reference)
#include <cuda_runtime.h>
#include <cuda_bf16.h>
#include <cstdint>
#include <cstddef>

#define B_ 1024
#define E_ 8192
#define R_ 16
#define D_ 128
#define BT 64            // b per tile (A rows: 64 h + 64 t = 128)
#define ET2 128          // e per tile (N)
#define NTILE_E (E_/ET2) // 64

// ---- global scratch (no allocation allowed) ----
__device__ float g_c[R_*E_];       // c[r,e] = zz[e] - 2*rz[r,e]
__device__ float g_g[E_];          // g[e]   = zz[e] + 2*zq[e]
__device__ float g_u[B_*R_];       // u[b,r] = hh[b] + rr[r] + 2*hr[b,r]
__device__ float g_v[B_];          // v[b]   = tt[b] + qq - 2*qt[b]
__device__ float g_part[B_*NTILE_E];
__device__ __nv_bfloat16 g_Ebf[E_*D_];

__device__ __forceinline__ float wsum(float v){
  v += __shfl_xor_sync(0xffffffffu, v, 16);
  v += __shfl_xor_sync(0xffffffffu, v, 8);
  v += __shfl_xor_sync(0xffffffffu, v, 4);
  v += __shfl_xor_sync(0xffffffffu, v, 2);
  v += __shfl_xor_sync(0xffffffffu, v, 1);
  return v;
}
__device__ __forceinline__ float dot4(float4 a, float4 b){
  return fmaf(a.x,b.x, fmaf(a.y,b.y, fmaf(a.z,b.z, a.w*b.w)));
}
__device__ __forceinline__ float sqrt_approx(float x){
  float y; asm("sqrt.approx.f32 %0, %1;" : "=f"(y) : "f"(x)); return y;
}
__device__ __forceinline__ uint32_t smem_u32(const void* p){
  uint32_t a;
  asm("{ .reg .u64 t; cvta.to.shared.u64 t, %1; cvt.u32.u64 %0, t; }" : "=r"(a) : "l"(p));
  return a;
}
__device__ __forceinline__ void ldm4(uint32_t& r0, uint32_t& r1, uint32_t& r2, uint32_t& r3,
                                     uint32_t addr){
  asm volatile("ldmatrix.sync.aligned.m8n8.x4.shared.b16 {%0,%1,%2,%3}, [%4];"
    : "=r"(r0), "=r"(r1), "=r"(r2), "=r"(r3) : "r"(addr));
}
__device__ __forceinline__ void mma16816(float* d, const uint32_t* a, uint32_t b0, uint32_t b1){
  asm volatile("mma.sync.aligned.m16n8k16.row.col.f32.bf16.bf16.f32 "
    "{%0,%1,%2,%3}, {%4,%5,%6,%7}, {%8,%9}, {%0,%1,%2,%3};"
    : "+f"(d[0]), "+f"(d[1]), "+f"(d[2]), "+f"(d[3])
    : "r"(a[0]), "r"(a[1]), "r"(a[2]), "r"(a[3]), "r"(b0), "r"(b1));
}

// ---------------- per-entity precompute: zz, g, c + bf16 convert ----------------
__global__ void k_pre_e(const float* __restrict__ Etab,
                        const float* __restrict__ rules,
                        const int* __restrict__ qrelp){
  __shared__ __align__(16) float rs[R_*D_];
  int tid = threadIdx.x;
  for (int i = tid; i < R_*D_; i += blockDim.x) rs[i] = rules[i];
  __syncthreads();
  int qrel = *qrelp;
  int lane = tid & 31, warp = tid >> 5;
  int e = blockIdx.x*8 + warp;
  float4 zv = ((const float4*)(Etab + (size_t)e*D_))[lane];
  // write bf16 table (fused former k_conv)
  {
    unsigned short s0 = __bfloat16_as_ushort(__float2bfloat16(zv.x));
    unsigned short s1 = __bfloat16_as_ushort(__float2bfloat16(zv.y));
    unsigned short s2 = __bfloat16_as_ushort(__float2bfloat16(zv.z));
    unsigned short s3 = __bfloat16_as_ushort(__float2bfloat16(zv.w));
    uint2 u;
    u.x = (uint32_t)s0 | ((uint32_t)s1 << 16);
    u.y = (uint32_t)s2 | ((uint32_t)s3 << 16);
    ((uint2*)(g_Ebf + (size_t)e*D_))[lane] = u;
  }
  float zz = wsum(dot4(zv, zv));
  float4 qv = ((const float4*)(rs + qrel*D_))[lane];
  float zq = wsum(dot4(zv, qv));
  if (lane == 0) g_g[e] = zz + 2.f*zq;
  #pragma unroll
  for (int r = 0; r < R_; r++){
    float4 rv = ((const float4*)(rs + r*D_))[lane];
    float rz = wsum(dot4(zv, rv));
    if (lane == 0) g_c[r*E_ + e] = zz - 2.f*rz;
  }
}

// ---------------- per-batch precompute: u, v ----------------
__global__ void k_pre_b(const float* __restrict__ Etab,
                        const float* __restrict__ rules,
                        const int* __restrict__ head,
                        const int* __restrict__ tail,
                        const int* __restrict__ qrelp){
  __shared__ __align__(16) float rs[R_*D_];
  __shared__ float rr[R_];
  int tid = threadIdx.x;
  for (int i = tid; i < R_*D_; i += blockDim.x) rs[i] = rules[i];
  __syncthreads();
  if (tid < R_){
    float s = 0.f;
    for (int k = 0; k < D_; k++) s = fmaf(rs[tid*D_+k], rs[tid*D_+k], s);
    rr[tid] = s;
  }
  __syncthreads();
  int qrel = *qrelp;
  int lane = tid & 31, warp = tid >> 5;
  int b = blockIdx.x*8 + warp;
  float4 hv = ((const float4*)(Etab + (size_t)head[b]*D_))[lane];
  float4 tv = ((const float4*)(Etab + (size_t)tail[b]*D_))[lane];
  float hh = wsum(dot4(hv, hv));
  float tt = wsum(dot4(tv, tv));
  float4 qv = ((const float4*)(rs + qrel*D_))[lane];
  float tq = wsum(dot4(tv, qv));
  if (lane == 0) g_v[b] = tt + rr[qrel] - 2.f*tq;
  #pragma unroll
  for (int r = 0; r < R_; r++){
    float4 rv = ((const float4*)(rs + r*D_))[lane];
    float hr = wsum(dot4(hv, rv));
    if (lane == 0) g_u[b*R_ + r] = hh + rr[r] + 2.f*hr;
  }
}

// ---------------- main mma.sync fused kernel ----------------
#define OFF_B 32768
#define OFF_US 67584
#define OFF_CS 71680
#define OFF_GS 79872
#define OFF_VS 80384
#define OFF_HIX 80640
#define OFF_TIX 80896
#define OFF_RED 81152
#define SMEM_BYTES 81664
#define SP 132   // stage pitch (floats)

__global__ __launch_bounds__(256,2) void k_main(const int* __restrict__ head,
                                                const int* __restrict__ tail){
  extern __shared__ __align__(16) char smc[];
  uint32_t sb = smem_u32(smc);
  float* stage = (float*)smc;
  float* us = (float*)(smc + OFF_US);
  float* cs = (float*)(smc + OFF_CS);
  float* gs = (float*)(smc + OFF_GS);
  float* vs = (float*)(smc + OFF_VS);
  int* hix = (int*)(smc + OFF_HIX);
  int* tix = (int*)(smc + OFF_TIX);
  float* red = (float*)(smc + OFF_RED);   // [8 warps][16 b]

  int tid = threadIdx.x, wid = tid >> 5, lane = tid & 31;
  int e0 = blockIdx.x * ET2, b0 = blockIdx.y * BT;

  if (tid < 64){ hix[tid] = head[b0+tid]; tix[tid] = tail[b0+tid]; vs[tid] = g_v[b0+tid]; }
  if (tid >= 128) gs[tid-128] = g_g[e0 + tid - 128];
  for (int i = tid; i < BT*R_; i += 256) us[i] = g_u[b0*R_ + i];
  for (int i = tid; i < R_*ET2; i += 256){
    int r = i >> 7, e = i & 127;
    cs[i] = g_c[r*E_ + e0 + e];
  }

  // ---- load bf16 tiles into swizzled SMEM (16B chunk ^= row&7) ----
  const uint4* T = (const uint4*)g_Ebf;   // 16 uint4 per entity row
  #pragma unroll
  for (int it = 0; it < 16; it++){
    int idx = it*256 + tid;
    int ch = idx & 15, row = (idx >> 4) & 127, sel = idx >> 11;  // 0:A 1:B
    int ent = sel ? (e0 + row) : ((row < 64) ? hix[row] : tix[row-64]);
    uint4 v = T[ent*16 + ch];
    *(uint4*)(smc + sel*OFF_B + row*256 + (((uint32_t)ch ^ (row & 7)) << 4)) = v;
  }
  __syncthreads();

  // ---- mma.sync: D[128 rows][128 cols]; warp (wm, wn) owns 64x32 ----
  int wm = wid >> 2, wn = wid & 3;
  int lrow = lane & 15, lhi = lane >> 4;

  uint32_t a_base[4], b_base[2];
  uint32_t a_sw[4], b_sw[2];
  #pragma unroll
  for (int mi = 0; mi < 4; mi++){
    int r = wm*64 + mi*16 + lrow;
    a_base[mi] = sb + r*256; a_sw[mi] = (uint32_t)(r & 7);
  }
  #pragma unroll
  for (int nj = 0; nj < 2; nj++){
    int r = wn*32 + nj*16 + lrow;
    b_base[nj] = sb + OFF_B + r*256; b_sw[nj] = (uint32_t)(r & 7);
  }

  float acc[4][4][4];
  #pragma unroll
  for (int mi = 0; mi < 4; mi++)
    #pragma unroll
    for (int ni = 0; ni < 4; ni++)
      #pragma unroll
      for (int q = 0; q < 4; q++) acc[mi][ni][q] = 0.f;

  #pragma unroll
  for (int kk = 0; kk < 8; kk++){
    uint32_t c = (uint32_t)(kk*2 + lhi);
    uint32_t ra[4][4], rb[2][4];
    #pragma unroll
    for (int mi = 0; mi < 4; mi++)
      ldm4(ra[mi][0], ra[mi][1], ra[mi][2], ra[mi][3],
           a_base[mi] + ((c ^ a_sw[mi]) << 4));
    #pragma unroll
    for (int nj = 0; nj < 2; nj++)
      ldm4(rb[nj][0], rb[nj][1], rb[nj][2], rb[nj][3],
           b_base[nj] + ((c ^ b_sw[nj]) << 4));
    #pragma unroll
    for (int mi = 0; mi < 4; mi++)
      #pragma unroll
      for (int ni = 0; ni < 4; ni++){
        int nj = ni >> 1, sub = ni & 1;
        mma16816(acc[mi][ni], ra[mi], rb[nj][sub], rb[nj][2+sub]);
      }
  }

  __syncthreads();   // everyone done reading tiles before stage overwrite

  // ---- write D to stage [128][SP] (rows 0-63 hz, 64-127 zt) ----
  {
    int rb0 = wm*64 + (lane >> 2);
    int cb0 = wn*32 + (lane & 3)*2;
    #pragma unroll
    for (int mi = 0; mi < 4; mi++)
      #pragma unroll
      for (int ni = 0; ni < 4; ni++){
        *(float2*)(stage + (rb0 + mi*16)*SP + cb0 + ni*8)
          = make_float2(acc[mi][ni][0], acc[mi][ni][1]);
        *(float2*)(stage + (rb0 + mi*16 + 8)*SP + cb0 + ni*8)
          = make_float2(acc[mi][ni][2], acc[mi][ni][3]);
      }
  }
  __syncthreads();

  // ---- epilogue: warp w -> b group (w>>1)*16..+16, e half (w&1)*64..+64 ----
  {
    int bgrp = wid >> 1, eh = wid & 1;
    int el = eh*64 + lane*2;                 // 2 e's per lane

    // cr slice into registers: 16 r x 2 e = 32 regs
    float2 crg[16];
    #pragma unroll
    for (int r = 0; r < R_; r++) crg[r] = *(const float2*)(cs + r*128 + el);
    float2 gg = *(const float2*)(gs + el);

    #pragma unroll
    for (int i = 0; i < 16; i++){
      int bl = bgrp*16 + i;
      float vb = vs[bl];
      float2 hz2 = *(const float2*)(stage + bl*SP + el);
      float2 zt2 = *(const float2*)(stage + (64+bl)*SP + el);
      float s2x = sqrt_approx(fmaxf(fmaf(-2.f, zt2.x, vb + gg.x), 0.f));
      float s2y = sqrt_approx(fmaxf(fmaf(-2.f, zt2.y, vb + gg.y), 0.f));
      // ur row into registers (broadcast LDS.128 x4)
      float4 u0 = *(const float4*)(us + bl*R_ + 0);
      float4 u1 = *(const float4*)(us + bl*R_ + 4);
      float4 u2 = *(const float4*)(us + bl*R_ + 8);
      float4 u3 = *(const float4*)(us + bl*R_ + 12);
      float ur[16] = {u0.x,u0.y,u0.z,u0.w, u1.x,u1.y,u1.z,u1.w,
                      u2.x,u2.y,u2.z,u2.w, u3.x,u3.y,u3.z,u3.w};
      float S1x = 0.f, S1y = 0.f;
      #pragma unroll
      for (int r = 0; r < R_; r++){
        S1x += sqrt_approx(fmaxf(fmaf(-2.f, hz2.x, ur[r] + crg[r].x), 0.f));
        S1y += sqrt_approx(fmaxf(fmaf(-2.f, hz2.y, ur[r] + crg[r].y), 0.f));
      }
      float a = fmaf(S1x, s2x, S1y*s2y);
      a = wsum(a);
      if (lane == 0) red[wid*16 + i] = a;
    }
  }
  __syncthreads();
  if (tid < 64){
    int bg = tid >> 4, i = tid & 15;
    float s = red[(bg*2)*16 + i] + red[(bg*2+1)*16 + i];
    g_part[(size_t)(b0 + tid)*NTILE_E + blockIdx.x] = s;
  }
}

// ---------------- final deterministic reduction ----------------
__global__ void k_final(float* __restrict__ out){
  int warp = threadIdx.x >> 5, lane = threadIdx.x & 31;
  int b = blockIdx.x*8 + warp;
  const float* p = g_part + (size_t)b*NTILE_E;
  float s = p[lane] + p[lane+32];
  s = wsum(s);
  if (lane == 0) out[b] = s * (1.f/(float)E_);
}

extern "C" void kernel_launch(void* const* d_in, const int* in_sizes, int n_in,
                              void* d_out, int out_size){
  const int*   head  = (const int*)d_in[0];
  const int*   tail  = (const int*)d_in[1];
  const int*   qrel  = (const int*)d_in[2];
  // d_in[3] = depth (fixed at 1, unused)
  const float* Etab  = (const float*)d_in[4];
  const float* rules = (const float*)d_in[5];
  float* out = (float*)d_out;

  cudaFuncSetAttribute(k_main, cudaFuncAttributeMaxDynamicSharedMemorySize, SMEM_BYTES);

  k_pre_e<<<E_/8, 256>>>(Etab, rules, qrel);
  k_pre_b<<<B_/8, 256>>>(Etab, rules, head, tail, qrel);
  dim3 grid(NTILE_E, B_/BT);
  k_main<<<grid, 256, SMEM_BYTES>>>(head, tail);
  k_final<<<B_/8, 256>>>(out);
}

// round 9
// speedup vs baseline: 1.0579x; 1.0579x over previous
#include <cuda_runtime.h>
#include <cuda_bf16.h>
#include <cstdint>
#include <cstddef>

#define B_ 1024
#define E_ 8192
#define R_ 16
#define D_ 128
#define BT 64            // b per tile (A rows: 64 h + 64 t = 128, 8-row interleaved)
#define ET2 128          // e per tile (N)
#define NTILE_E (E_/ET2) // 64

// ---- global scratch (no allocation allowed) ----
__device__ float g_c[R_*E_];       // c[r,e] = zz[e] - 2*rz[r,e]
__device__ float g_g[E_];          // g[e]   = zz[e] + 2*zq[e]
__device__ float g_u[B_*R_];       // u[b,r] = hh[b] + rr[r] + 2*hr[b,r]
__device__ float g_v[B_];          // v[b]   = tt[b] + qq - 2*qt[b]
__device__ float g_part[B_*NTILE_E];
__device__ __nv_bfloat16 g_Ebf[E_*D_];

__device__ __forceinline__ float wsum(float v){
  v += __shfl_xor_sync(0xffffffffu, v, 16);
  v += __shfl_xor_sync(0xffffffffu, v, 8);
  v += __shfl_xor_sync(0xffffffffu, v, 4);
  v += __shfl_xor_sync(0xffffffffu, v, 2);
  v += __shfl_xor_sync(0xffffffffu, v, 1);
  return v;
}
__device__ __forceinline__ float dot4(float4 a, float4 b){
  return fmaf(a.x,b.x, fmaf(a.y,b.y, fmaf(a.z,b.z, a.w*b.w)));
}
__device__ __forceinline__ float sqrt_approx(float x){
  float y; asm("sqrt.approx.f32 %0, %1;" : "=f"(y) : "f"(x)); return y;
}
__device__ __forceinline__ uint32_t smem_u32(const void* p){
  uint32_t a;
  asm("{ .reg .u64 t; cvta.to.shared.u64 t, %1; cvt.u32.u64 %0, t; }" : "=r"(a) : "l"(p));
  return a;
}
__device__ __forceinline__ void ldm4(uint32_t& r0, uint32_t& r1, uint32_t& r2, uint32_t& r3,
                                     uint32_t addr){
  asm volatile("ldmatrix.sync.aligned.m8n8.x4.shared.b16 {%0,%1,%2,%3}, [%4];"
    : "=r"(r0), "=r"(r1), "=r"(r2), "=r"(r3) : "r"(addr));
}
__device__ __forceinline__ void mma16816(float* d, const uint32_t* a, uint32_t b0, uint32_t b1){
  asm volatile("mma.sync.aligned.m16n8k16.row.col.f32.bf16.bf16.f32 "
    "{%0,%1,%2,%3}, {%4,%5,%6,%7}, {%8,%9}, {%0,%1,%2,%3};"
    : "+f"(d[0]), "+f"(d[1]), "+f"(d[2]), "+f"(d[3])
    : "r"(a[0]), "r"(a[1]), "r"(a[2]), "r"(a[3]), "r"(b0), "r"(b1));
}

// ---------------- merged precompute: entity part + batch part ----------------
__global__ void k_pre(const float* __restrict__ Etab,
                      const float* __restrict__ rules,
                      const int* __restrict__ head,
                      const int* __restrict__ tail,
                      const int* __restrict__ qrelp){
  __shared__ __align__(16) float rs[R_*D_];
  __shared__ float rr[R_];
  int tid = threadIdx.x;
  for (int i = tid; i < R_*D_; i += blockDim.x) rs[i] = rules[i];
  __syncthreads();
  if (tid < R_){
    float s = 0.f;
    for (int k = 0; k < D_; k++) s = fmaf(rs[tid*D_+k], rs[tid*D_+k], s);
    rr[tid] = s;
  }
  __syncthreads();
  int qrel = *qrelp;
  int lane = tid & 31, warp = tid >> 5;

  if (blockIdx.x < E_/8){
    // entity part: zz, g, c + bf16 convert
    int e = blockIdx.x*8 + warp;
    float4 zv = ((const float4*)(Etab + (size_t)e*D_))[lane];
    {
      unsigned short s0 = __bfloat16_as_ushort(__float2bfloat16(zv.x));
      unsigned short s1 = __bfloat16_as_ushort(__float2bfloat16(zv.y));
      unsigned short s2 = __bfloat16_as_ushort(__float2bfloat16(zv.z));
      unsigned short s3 = __bfloat16_as_ushort(__float2bfloat16(zv.w));
      uint2 u;
      u.x = (uint32_t)s0 | ((uint32_t)s1 << 16);
      u.y = (uint32_t)s2 | ((uint32_t)s3 << 16);
      ((uint2*)(g_Ebf + (size_t)e*D_))[lane] = u;
    }
    float zz = wsum(dot4(zv, zv));
    float4 qv = ((const float4*)(rs + qrel*D_))[lane];
    float zq = wsum(dot4(zv, qv));
    if (lane == 0) g_g[e] = zz + 2.f*zq;
    #pragma unroll
    for (int r = 0; r < R_; r++){
      float4 rv = ((const float4*)(rs + r*D_))[lane];
      float rz = wsum(dot4(zv, rv));
      if (lane == 0) g_c[r*E_ + e] = zz - 2.f*rz;
    }
  } else {
    // batch part: u, v
    int b = (blockIdx.x - E_/8)*8 + warp;
    float4 hv = ((const float4*)(Etab + (size_t)head[b]*D_))[lane];
    float4 tv = ((const float4*)(Etab + (size_t)tail[b]*D_))[lane];
    float hh = wsum(dot4(hv, hv));
    float tt = wsum(dot4(tv, tv));
    float4 qv = ((const float4*)(rs + qrel*D_))[lane];
    float tq = wsum(dot4(tv, qv));
    if (lane == 0) g_v[b] = tt + rr[qrel] - 2.f*tq;
    #pragma unroll
    for (int r = 0; r < R_; r++){
      float4 rv = ((const float4*)(rs + r*D_))[lane];
      float hr = wsum(dot4(hv, rv));
      if (lane == 0) g_u[b*R_ + r] = hh + rr[r] + 2.f*hr;
    }
  }
}

// ---------------- main mma.sync fused kernel ----------------
// SMEM (bytes): A tile @0 (32KB), B tile @32768 (32KB),
// us @65536 (4KB), cs @69632 (8KB), gs @77824 (512), vs @78336 (256),
// hix @78592, tix @78848, red @79104 (1KB) -> 80128 total
#define OFF_B   32768
#define OFF_US  65536
#define OFF_CS  69632
#define OFF_GS  77824
#define OFF_VS  78336
#define OFF_HIX 78592
#define OFF_TIX 78848
#define OFF_RED 79104
#define SMEM_BYTES 80128

__global__ __launch_bounds__(256,2) void k_main(const int* __restrict__ head,
                                                const int* __restrict__ tail){
  extern __shared__ __align__(16) char smc[];
  uint32_t sb = smem_u32(smc);
  float* us = (float*)(smc + OFF_US);    // [64][16]
  float* cs = (float*)(smc + OFF_CS);    // [16][128]
  float* gs = (float*)(smc + OFF_GS);    // [128]
  float* vs = (float*)(smc + OFF_VS);    // [64]
  int* hix = (int*)(smc + OFF_HIX);
  int* tix = (int*)(smc + OFF_TIX);
  float* red = (float*)(smc + OFF_RED);  // [4][64]

  int tid = threadIdx.x, wid = tid >> 5, lane = tid & 31;
  int e0 = blockIdx.x * ET2, b0 = blockIdx.y * BT;

  if (tid < 64){ hix[tid] = head[b0+tid]; tix[tid] = tail[b0+tid]; vs[tid] = g_v[b0+tid]; }
  if (tid >= 128) gs[tid-128] = g_g[e0 + tid - 128];
  for (int i = tid; i < BT*R_; i += 256) us[i] = g_u[b0*R_ + i];
  for (int i = tid; i < R_*ET2; i += 256){
    int r = i >> 7, e = i & 127;
    cs[i] = g_c[r*E_ + e0 + e];
  }

  // ---- load bf16 tiles into swizzled SMEM (16B chunk ^= row&7) ----
  // A rows interleaved in 8-blocks: row -> b_local = ((row>>4)<<3)|(row&7),
  // (row&8) selects t vs h. This puts hz and zt for the SAME b into one
  // thread's mma fragment (rows r and r+8 of each m16 tile).
  const uint4* T = (const uint4*)g_Ebf;   // 16 uint4 per entity row
  #pragma unroll
  for (int it = 0; it < 16; it++){
    int idx = it*256 + tid;
    int ch = idx & 15, row = (idx >> 4) & 127, sel = idx >> 11;  // 0:A 1:B
    int ent;
    if (sel){ ent = e0 + row; }
    else {
      int bl = ((row >> 4) << 3) | (row & 7);
      ent = (row & 8) ? tix[bl] : hix[bl];
    }
    uint4 v = T[ent*16 + ch];
    *(uint4*)(smc + sel*OFF_B + row*256 + (((uint32_t)ch ^ (row & 7)) << 4)) = v;
  }
  __syncthreads();

  // ---- mma.sync: warp (wm, wn) owns A rows wm*64..+64, e cols wn*32..+32 ----
  int wm = wid >> 2, wn = wid & 3;
  int lrow = lane & 15, lhi = lane >> 4;

  uint32_t a_base[4], b_base[2];
  uint32_t a_sw[4], b_sw[2];
  #pragma unroll
  for (int mi = 0; mi < 4; mi++){
    int r = wm*64 + mi*16 + lrow;
    a_base[mi] = sb + r*256; a_sw[mi] = (uint32_t)(r & 7);
  }
  #pragma unroll
  for (int nj = 0; nj < 2; nj++){
    int r = wn*32 + nj*16 + lrow;
    b_base[nj] = sb + OFF_B + r*256; b_sw[nj] = (uint32_t)(r & 7);
  }

  float acc[4][4][4];
  #pragma unroll
  for (int mi = 0; mi < 4; mi++)
    #pragma unroll
    for (int ni = 0; ni < 4; ni++)
      #pragma unroll
      for (int q = 0; q < 4; q++) acc[mi][ni][q] = 0.f;

  #pragma unroll
  for (int kk = 0; kk < 8; kk++){
    uint32_t c = (uint32_t)(kk*2 + lhi);
    uint32_t ra[4][4], rb[2][4];
    #pragma unroll
    for (int mi = 0; mi < 4; mi++)
      ldm4(ra[mi][0], ra[mi][1], ra[mi][2], ra[mi][3],
           a_base[mi] + ((c ^ a_sw[mi]) << 4));
    #pragma unroll
    for (int nj = 0; nj < 2; nj++)
      ldm4(rb[nj][0], rb[nj][1], rb[nj][2], rb[nj][3],
           b_base[nj] + ((c ^ b_sw[nj]) << 4));
    #pragma unroll
    for (int mi = 0; mi < 4; mi++)
      #pragma unroll
      for (int ni = 0; ni < 4; ni++){
        int nj = ni >> 1, sub = ni & 1;
        mma16816(acc[mi][ni], ra[mi], rb[nj][sub], rb[nj][2+sub]);
      }
  }

  // ---- in-register epilogue ----
  // thread owns: b[mi] = (wm*4+mi)*8 + (lane>>2), e[ni][col] = wn*32+ni*8+(lane&3)*2+col
  // acc[mi][ni][0..1] = hz(b, e/e+1); acc[mi][ni][2..3] = zt(b, e/e+1)
  int brow = lane >> 2, ecol = (lane & 3)*2;
  int eb = wn*32 + ecol;

  // s2 -> overwrite acc[..][2..3]
  #pragma unroll
  for (int ni = 0; ni < 4; ni++){
    float2 gg = *(const float2*)(gs + eb + ni*8);
    #pragma unroll
    for (int mi = 0; mi < 4; mi++){
      int bl = (wm*4 + mi)*8 + brow;
      float vb = vs[bl];
      acc[mi][ni][2] = sqrt_approx(fmaxf(fmaf(-2.f, acc[mi][ni][2], vb + gg.x), 0.f));
      acc[mi][ni][3] = sqrt_approx(fmaxf(fmaf(-2.f, acc[mi][ni][3], vb + gg.y), 0.f));
    }
  }

  // S1 accumulation over r
  float S1[4][4][2];
  #pragma unroll
  for (int mi = 0; mi < 4; mi++)
    #pragma unroll
    for (int ni = 0; ni < 4; ni++){ S1[mi][ni][0] = 0.f; S1[mi][ni][1] = 0.f; }

  #pragma unroll
  for (int r = 0; r < R_; r++){
    float2 cr[4];
    #pragma unroll
    for (int ni = 0; ni < 4; ni++) cr[ni] = *(const float2*)(cs + r*128 + eb + ni*8);
    #pragma unroll
    for (int mi = 0; mi < 4; mi++){
      int bl = (wm*4 + mi)*8 + brow;
      float ur = us[bl*R_ + r];
      #pragma unroll
      for (int ni = 0; ni < 4; ni++){
        S1[mi][ni][0] += sqrt_approx(fmaxf(fmaf(-2.f, acc[mi][ni][0], ur + cr[ni].x), 0.f));
        S1[mi][ni][1] += sqrt_approx(fmaxf(fmaf(-2.f, acc[mi][ni][1], ur + cr[ni].y), 0.f));
      }
    }
  }

  // combine S1*s2, reduce over this thread's 8 e's, then over the quad
  #pragma unroll
  for (int mi = 0; mi < 4; mi++){
    float s = 0.f;
    #pragma unroll
    for (int ni = 0; ni < 4; ni++)
      s = fmaf(S1[mi][ni][0], acc[mi][ni][2], fmaf(S1[mi][ni][1], acc[mi][ni][3], s));
    s += __shfl_xor_sync(0xffffffffu, s, 1);
    s += __shfl_xor_sync(0xffffffffu, s, 2);
    if ((lane & 3) == 0){
      int bl = (wm*4 + mi)*8 + brow;
      red[wn*64 + bl] = s;
    }
  }
  __syncthreads();
  if (tid < 64){
    float s = red[tid] + red[64+tid] + red[128+tid] + red[192+tid];
    g_part[(size_t)(b0 + tid)*NTILE_E + blockIdx.x] = s;
  }
}

// ---------------- final deterministic reduction ----------------
__global__ void k_final(float* __restrict__ out){
  int warp = threadIdx.x >> 5, lane = threadIdx.x & 31;
  int b = blockIdx.x*8 + warp;
  const float* p = g_part + (size_t)b*NTILE_E;
  float s = p[lane] + p[lane+32];
  s = wsum(s);
  if (lane == 0) out[b] = s * (1.f/(float)E_);
}

extern "C" void kernel_launch(void* const* d_in, const int* in_sizes, int n_in,
                              void* d_out, int out_size){
  const int*   head  = (const int*)d_in[0];
  const int*   tail  = (const int*)d_in[1];
  const int*   qrel  = (const int*)d_in[2];
  // d_in[3] = depth (fixed at 1, unused)
  const float* Etab  = (const float*)d_in[4];
  const float* rules = (const float*)d_in[5];
  float* out = (float*)d_out;

  cudaFuncSetAttribute(k_main, cudaFuncAttributeMaxDynamicSharedMemorySize, SMEM_BYTES);

  k_pre<<<E_/8 + B_/8, 256>>>(Etab, rules, head, tail, qrel);
  dim3 grid(NTILE_E, B_/BT);
  k_main<<<grid, 256, SMEM_BYTES>>>(head, tail);
  k_final<<<B_/8, 256>>>(out);
}